// round 11
// baseline (speedup 1.0000x reference)
#include <cuda_runtime.h>
#include <math_constants.h>

// ---------------- problem constants ----------------
#define BB 2
#define NV 6
#define DIMC 128
#define QCNT 2304   // 48*48
#define KCNT 576    // 24*24
#define HEADS 4
#define DH 32
#define BH (BB*HEADS)          // 8
#define NSPLIT 2
#define KSPL (KCNT/NSPLIT)     // 288
#define NPART (NV*NSPLIT)      // 12
#define CHK 72                 // attn chunk keys (4 chunks of 72)
#define SCALEF 0.17677669529663689f  // 32^-0.5

typedef unsigned long long u64;

// ---------------- f32x2 packed helpers ----------------
__device__ __forceinline__ u64 f2_fma(u64 a, u64 b, u64 c) {
    u64 d; asm("fma.rn.f32x2 %0,%1,%2,%3;" : "=l"(d) : "l"(a), "l"(b), "l"(c)); return d;
}
__device__ __forceinline__ u64 f2_mul(u64 a, u64 b) {
    u64 d; asm("mul.rn.f32x2 %0,%1,%2;" : "=l"(d) : "l"(a), "l"(b)); return d;
}
__device__ __forceinline__ u64 f2_add(u64 a, u64 b) {
    u64 d; asm("add.rn.f32x2 %0,%1,%2;" : "=l"(d) : "l"(a), "l"(b)); return d;
}
__device__ __forceinline__ u64 f2_dup(float x) {
    u64 d; asm("mov.b64 %0,{%1,%1};" : "=l"(d) : "r"(__float_as_uint(x))); return d;
}
__device__ __forceinline__ void f2_unpack(float& lo, float& hi, u64 v) {
    unsigned a, b; asm("mov.b64 {%0,%1},%2;" : "=r"(a), "=r"(b) : "l"(v));
    lo = __uint_as_float(a); hi = __uint_as_float(b);
}
__device__ __forceinline__ unsigned s2u(const void* p) {
    unsigned r;
    asm("{.reg .u64 t; cvta.to.shared.u64 t, %1; cvt.u32.u64 %0, t;}" : "=r"(r) : "l"(p));
    return r;
}
__device__ __forceinline__ void cpa16(unsigned s, const void* g) {
    asm volatile("cp.async.cg.shared.global [%0], [%1], 16;" :: "r"(s), "l"(g));
}

// ---------------- scratch (device globals; no allocation allowed) ----------------
__device__ float g_qp[BH * NV * QCNT * DH];
__device__ float g_kp[BH * NV * KCNT * DH];
__device__ float g_vp[BH * NV * KCNT * DH];
__device__ float g_Opart[BH * NPART * QCNT * DH];
__device__ float g_ml[BH * NPART * QCNT * 2];

// ==================================================================
// Kernel 1: LN + projection for q,k,v in ONE launch. 64-row tiles.
// q: blocks [0,432), k: [432,540), v: [540,648).  256 threads.
// Dynamic smem: As[64*129] + Wsm[64*128] = 65792 B -> 3 blocks/SM.
// W staged in two k-halves. Threads: rg = tid&15 owns rows rg+16i
// (conflict-free), c0 = (tid>>4)*8 (W broadcast). q pre-scaled.
// ==================================================================
#define PJS 129
__global__ __launch_bounds__(256, 3) void proj_all_kernel(
    const float* __restrict__ qi, const float* __restrict__ ki, const float* __restrict__ vi,
    const float* __restrict__ lnqg, const float* __restrict__ lnqb,
    const float* __restrict__ Wq, const float* __restrict__ bq,
    const float* __restrict__ lnkg, const float* __restrict__ lnkb,
    const float* __restrict__ Wk, const float* __restrict__ bk,
    const float* __restrict__ lnvg, const float* __restrict__ lnvb,
    const float* __restrict__ Wv, const float* __restrict__ bv,
    float* __restrict__ qo, float* __restrict__ ko, float* __restrict__ vo)
{
    extern __shared__ float dynP[];
    float* As  = dynP;                  // 64*129
    float* Wsm = dynP + 64 * PJS;       // 64*128
    __shared__ float s_mean[64], s_rstd[64];
    int blk = blockIdx.x;
    int tid = threadIdx.x;

    const float* X; const float* lng; const float* lnb;
    const float* Wt; const float* biasv; float* outp; int S, local; float oscale;
    if (blk < 432)      { X = qi; lng = lnqg; lnb = lnqb; Wt = Wq; biasv = bq; outp = qo; S = QCNT; local = blk;       oscale = SCALEF; }
    else if (blk < 540) { X = ki; lng = lnkg; lnb = lnkb; Wt = Wk; biasv = bk; outp = ko; S = KCNT; local = blk - 432; oscale = 1.f; }
    else                { X = vi; lng = lnvg; lnb = lnvb; Wt = Wv; biasv = bv; outp = vo; S = KCNT; local = blk - 540; oscale = 1.f; }

    int tiles = S >> 6;
    int t = local % tiles;
    int bn = local / tiles;            // b*6+n
    int b = bn / NV, n = bn % NV;
    int s0 = t * 64;
    const float* Xb = X + (size_t)bn * DIMC * S;

    // load A tile (coalesced) + stage W k-half0
    for (int idx = tid; idx < 64 * 128; idx += 256) {
        int c = idx >> 6, r = idx & 63;
        As[r * PJS + c] = Xb[(size_t)c * S + s0 + r];
    }
    {
        const float4* Wg = (const float4*)Wt;
        float4* Ws4 = (float4*)Wsm;
        for (int i = tid; i < 2048; i += 256) Ws4[i] = Wg[i];
    }
    __syncthreads();
    // ---- LN stats: 4 threads per row, shfl butterfly ----
    {
        int r = tid >> 2, p = tid & 3;
        const float* row = &As[r * PJS];
        float s = 0.f, s2 = 0.f;
        #pragma unroll 8
        for (int ci = 0; ci < 32; ci++) { float x = row[p + 4 * ci]; s += x; s2 += x * x; }
        s  += __shfl_xor_sync(0xffffffffu, s, 1);
        s2 += __shfl_xor_sync(0xffffffffu, s2, 1);
        s  += __shfl_xor_sync(0xffffffffu, s, 2);
        s2 += __shfl_xor_sync(0xffffffffu, s2, 2);
        if (p == 0) {
            float mn = s * (1.f / 128.f);
            float vv = s2 * (1.f / 128.f) - mn * mn;
            s_mean[r] = mn; s_rstd[r] = rsqrtf(vv + 1e-5f);
        }
    }
    __syncthreads();
    for (int idx = tid; idx < 64 * 128; idx += 256) {
        int r = idx >> 7, c = idx & 127;
        As[r * PJS + c] = (As[r * PJS + c] - s_mean[r]) * s_rstd[r] * lng[c] + lnb[c];
    }
    __syncthreads();

    // GEMM 64x128 * 128x128 over two k-halves
    int rg = tid & 15;
    int c0 = (tid >> 4) * 8;
    u64 acc[4][4];
    #pragma unroll
    for (int i = 0; i < 4; i++)
        #pragma unroll
        for (int j = 0; j < 4; j++) acc[i][j] = 0ull;

    #pragma unroll 1
    for (int kk = 0; kk < 2; kk++) {
        #pragma unroll 4
        for (int k = 0; k < 64; k++) {
            const double* Wd = (const double*)(Wsm + k * 128 + c0);
            u64 w0 = __double_as_longlong(Wd[0]);
            u64 w1 = __double_as_longlong(Wd[1]);
            u64 w2 = __double_as_longlong(Wd[2]);
            u64 w3 = __double_as_longlong(Wd[3]);
            #pragma unroll
            for (int i = 0; i < 4; i++) {
                u64 av = f2_dup(As[(rg + 16 * i) * PJS + kk * 64 + k]);
                acc[i][0] = f2_fma(av, w0, acc[i][0]);
                acc[i][1] = f2_fma(av, w1, acc[i][1]);
                acc[i][2] = f2_fma(av, w2, acc[i][2]);
                acc[i][3] = f2_fma(av, w3, acc[i][3]);
            }
        }
        if (kk == 0) {
            __syncthreads();
            const float4* Wg = (const float4*)(Wt + 64 * 128);
            float4* Ws4 = (float4*)Wsm;
            for (int i = tid; i < 2048; i += 256) Ws4[i] = Wg[i];
            __syncthreads();
        }
    }
    const double* Bd = (const double*)(biasv + c0);
    u64 bb0 = __double_as_longlong(Bd[0]);
    u64 bb1 = __double_as_longlong(Bd[1]);
    u64 bb2 = __double_as_longlong(Bd[2]);
    u64 bb3 = __double_as_longlong(Bd[3]);
    u64 sc = f2_dup(oscale);
    int head = c0 >> 5, dh0 = c0 & 31;
    #pragma unroll
    for (int i = 0; i < 4; i++) {
        int qrow = s0 + rg + 16 * i;
        u64* dst = (u64*)(outp + ((((size_t)(b * HEADS + head) * NV + n) * S + qrow) * DH + dh0));
        dst[0] = f2_mul(f2_add(acc[i][0], bb0), sc);
        dst[1] = f2_mul(f2_add(acc[i][1], bb1), sc);
        dst[2] = f2_mul(f2_add(acc[i][2], bb2), sc);
        dst[3] = f2_mul(f2_add(acc[i][3], bb3), sc);
    }
}

// ==================================================================
// Kernel 2: per-(view,split) flash attention partials. 2 queries/thread.
// grid (18, 12, 8), 64 threads. 288 keys in 4x72 chunks, cp.async
// double-buffered. smem 36KB; 6 blocks/SM (reg cap 170).
// ==================================================================
__device__ __forceinline__ void attn_chunk(
    const float4* Ks, const float4* Vs,
    const u64 qu[2][16], u64 Ov[2][16],
    float& m0, float& m1, float& l0, float& l1)
{
    #pragma unroll 1
    for (int g = 0; g < CHK / 8; g++) {
        float sc0[8], sc1[8];
        #pragma unroll
        for (int j = 0; j < 8; j++) {
            const double2* Kr = (const double2*)&Ks[(g * 8 + j) * 8];
            u64 a00 = 0, a01 = 0, a10 = 0, a11 = 0;
            #pragma unroll
            for (int i = 0; i < 4; i++) {
                double2 d0 = Kr[2 * i];
                double2 d1 = Kr[2 * i + 1];
                u64 k0 = __double_as_longlong(d0.x), k1 = __double_as_longlong(d0.y);
                u64 k2 = __double_as_longlong(d1.x), k3 = __double_as_longlong(d1.y);
                a00 = f2_fma(qu[0][4 * i + 0], k0, a00);
                a01 = f2_fma(qu[0][4 * i + 1], k1, a01);
                a00 = f2_fma(qu[0][4 * i + 2], k2, a00);
                a01 = f2_fma(qu[0][4 * i + 3], k3, a01);
                a10 = f2_fma(qu[1][4 * i + 0], k0, a10);
                a11 = f2_fma(qu[1][4 * i + 1], k1, a11);
                a10 = f2_fma(qu[1][4 * i + 2], k2, a10);
                a11 = f2_fma(qu[1][4 * i + 3], k3, a11);
            }
            float lo, hi;
            f2_unpack(lo, hi, f2_add(a00, a01)); sc0[j] = lo + hi;
            f2_unpack(lo, hi, f2_add(a10, a11)); sc1[j] = lo + hi;
        }
        float gm0 = sc0[0], gm1 = sc1[0];
        #pragma unroll
        for (int j = 1; j < 8; j++) { gm0 = fmaxf(gm0, sc0[j]); gm1 = fmaxf(gm1, sc1[j]); }
        if (gm0 > m0) {
            float sf = __expf(m0 - gm0);   // m=-inf -> 0
            l0 *= sf;
            u64 s2 = f2_dup(sf);
            #pragma unroll
            for (int e = 0; e < 16; e++) Ov[0][e] = f2_mul(Ov[0][e], s2);
            m0 = gm0;
        }
        if (gm1 > m1) {
            float sf = __expf(m1 - gm1);
            l1 *= sf;
            u64 s2 = f2_dup(sf);
            #pragma unroll
            for (int e = 0; e < 16; e++) Ov[1][e] = f2_mul(Ov[1][e], s2);
            m1 = gm1;
        }
        #pragma unroll
        for (int j = 0; j < 8; j++) {
            float p0 = __expf(sc0[j] - m0); l0 += p0;
            float p1 = __expf(sc1[j] - m1); l1 += p1;
            u64 pp0 = f2_dup(p0);
            u64 pp1 = f2_dup(p1);
            const double2* Vr = (const double2*)&Vs[(g * 8 + j) * 8];
            #pragma unroll
            for (int i = 0; i < 4; i++) {
                double2 v0 = Vr[2 * i];
                double2 v1 = Vr[2 * i + 1];
                u64 x0 = __double_as_longlong(v0.x), x1 = __double_as_longlong(v0.y);
                u64 x2 = __double_as_longlong(v1.x), x3 = __double_as_longlong(v1.y);
                Ov[0][4 * i + 0] = f2_fma(pp0, x0, Ov[0][4 * i + 0]);
                Ov[0][4 * i + 1] = f2_fma(pp0, x1, Ov[0][4 * i + 1]);
                Ov[0][4 * i + 2] = f2_fma(pp0, x2, Ov[0][4 * i + 2]);
                Ov[0][4 * i + 3] = f2_fma(pp0, x3, Ov[0][4 * i + 3]);
                Ov[1][4 * i + 0] = f2_fma(pp1, x0, Ov[1][4 * i + 0]);
                Ov[1][4 * i + 1] = f2_fma(pp1, x1, Ov[1][4 * i + 1]);
                Ov[1][4 * i + 2] = f2_fma(pp1, x2, Ov[1][4 * i + 2]);
                Ov[1][4 * i + 3] = f2_fma(pp1, x3, Ov[1][4 * i + 3]);
            }
        }
    }
}

__global__ __launch_bounds__(64, 6) void attn_kernel(
    const float* __restrict__ qp, const float* __restrict__ kp,
    const float* __restrict__ vp, float* __restrict__ Opart,
    float* __restrict__ ml)
{
    __shared__ float4 Ksm[2][CHK * 8];
    __shared__ float4 Vsm[2][CHK * 8];
    int qt = blockIdx.x;
    int ns = blockIdx.y;                 // n*2 + split
    int bh = blockIdx.z;
    int n = ns >> 1, split = ns & 1;
    int tid = threadIdx.x;
    size_t view = (size_t)bh * NV + n;
    size_t view2 = view * NSPLIT + split;
    int base = split * KSPL;

    const float4* Kb = (const float4*)(kp + view * KCNT * DH);
    const float4* Vb = (const float4*)(vp + view * KCNT * DH);

    // issue a CHK-key (K,V) stage into buffer buf
    auto issue = [&](int st, int buf) {
        const float4* Kg = Kb + (size_t)(base + st * CHK) * 8;
        const float4* Vg = Vb + (size_t)(base + st * CHK) * 8;
        #pragma unroll
        for (int i = 0; i < CHK * 8 / 64; i++) {
            int f = i * 64 + tid;
            cpa16(s2u(&Ksm[buf][f]), Kg + f);
            cpa16(s2u(&Vsm[buf][f]), Vg + f);
        }
        asm volatile("cp.async.commit_group;");
    };

    issue(0, 0);
    issue(1, 1);

    u64 qu[2][16];
    #pragma unroll
    for (int s = 0; s < 2; s++) {
        const u64* qrow = (const u64*)(qp + (view * QCNT + qt * 128 + s * 64 + tid) * DH);
        #pragma unroll
        for (int e = 0; e < 16; e++) qu[s][e] = qrow[e];   // pre-scaled by SCALEF
    }
    u64 Ov[2][16];
    #pragma unroll
    for (int s = 0; s < 2; s++)
        #pragma unroll
        for (int e = 0; e < 16; e++) Ov[s][e] = 0ull;
    float m0 = -CUDART_INF_F, m1 = -CUDART_INF_F, l0 = 0.f, l1 = 0.f;

    asm volatile("cp.async.wait_group 1;");
    __syncthreads();
    attn_chunk(Ksm[0], Vsm[0], qu, Ov, m0, m1, l0, l1);
    __syncthreads();
    issue(2, 0);
    asm volatile("cp.async.wait_group 1;");
    __syncthreads();
    attn_chunk(Ksm[1], Vsm[1], qu, Ov, m0, m1, l0, l1);
    __syncthreads();
    issue(3, 1);
    asm volatile("cp.async.wait_group 1;");
    __syncthreads();
    attn_chunk(Ksm[0], Vsm[0], qu, Ov, m0, m1, l0, l1);
    __syncthreads();
    asm volatile("cp.async.wait_group 0;");
    __syncthreads();
    attn_chunk(Ksm[1], Vsm[1], qu, Ov, m0, m1, l0, l1);

    #pragma unroll
    for (int s = 0; s < 2; s++) {
        size_t orow = view2 * QCNT + qt * 128 + s * 64 + tid;
        u64* dst = (u64*)(Opart + orow * DH);
        #pragma unroll
        for (int e = 0; e < 16; e++) dst[e] = Ov[s][e];
        ml[orow * 2]     = s ? m1 : m0;
        ml[orow * 2 + 1] = s ? l1 : l0;
    }
}

// ==================================================================
// Kernel 3: fused combine(12) + out-proj + skip + preLN + MLP + postLN
//           + transposed store. 256 threads, 32-row tiles (144 blocks).
// Weights staged in 64-k-row halves (Wsm 32KB). smem ~72KB, 3 blocks/SM.
// Threads: rg = tid&15 owns rows rg, rg+16 (conflict-free);
//          c0 = (tid>>4)*8 (W broadcast).
// ==================================================================
#define CTP 130
#define TROWS 32
__global__ __launch_bounds__(256, 3) void tail_kernel(
    const float* __restrict__ Opart, const float* __restrict__ ml,
    const float* __restrict__ skip,
    const float* __restrict__ Wpm, const float* __restrict__ bpv,
    const float* __restrict__ preg, const float* __restrict__ preb,
    const float* __restrict__ W1m, const float* __restrict__ b1v,
    const float* __restrict__ W2m, const float* __restrict__ b2v,
    const float* __restrict__ postg, const float* __restrict__ postb,
    float* __restrict__ outp)
{
    extern __shared__ float dynT[];
    float* As  = dynT;                       // TROWS*CTP
    float* Bs  = As + TROWS * CTP;           // TROWS*CTP
    float* Wsm = Bs + TROWS * CTP;           // 64*128 = 8192
    float* sW  = Wsm + 8192;                 // TROWS*4*NPART = 1536
    __shared__ float sm[TROWS], sr[TROWS];
    int tid = threadIdx.x;
    int gr0 = blockIdx.x * TROWS;       // rows are b*2304+q
    int b = gr0 / QCNT, q0 = gr0 - b * QCNT;

    // stage-weight helper: 64 k-rows x 128 cols from row-major [.,ld]
    auto stageW = [&](const float* Wg0, int ld) {
        #pragma unroll 2
        for (int i = tid; i < 2048; i += 256) {
            int k = i >> 5, c4 = i & 31;
            ((float4*)Wsm)[k * 32 + c4] = ((const float4*)(Wg0 + (size_t)k * ld))[c4];
        }
    };

    // ---- combine weights (tid<128: one per (row, head)) + stage Wp k0 ----
    if (tid < 128) {
        int r = tid >> 2, head = tid & 3;
        int q = q0 + r;
        size_t bhx = (size_t)b * HEADS + head;
        size_t rowbase = (bhx * NPART) * QCNT + q;
        float mv[NPART], lv[NPART], M = -CUDART_INF_F;
        #pragma unroll
        for (int n2 = 0; n2 < NPART; n2++) {
            size_t row = rowbase + (size_t)n2 * QCNT;
            mv[n2] = ml[row * 2];
            lv[n2] = ml[row * 2 + 1];
            M = fmaxf(M, mv[n2]);
        }
        float L = 0.f;
        float w[NPART];
        #pragma unroll
        for (int n2 = 0; n2 < NPART; n2++) {
            w[n2] = __expf(mv[n2] - M);
            L += w[n2] * lv[n2];
        }
        float Linv = __fdividef(1.f, L);
        #pragma unroll
        for (int n2 = 0; n2 < NPART; n2++)
            sW[tid * NPART + n2] = w[n2] * Linv;
    }
    stageW(Wpm, 128);
    __syncthreads();

    // ---- combine 12 partials into As ----
    for (int idx = tid; idx < TROWS * 128; idx += 256) {
        int r = idx >> 7, c = idx & 127;
        int q = q0 + r;
        int head = c >> 5, dh = c & 31;
        size_t bhx = (size_t)b * HEADS + head;
        const float* wv = &sW[(r * 4 + head) * NPART];
        size_t obase = ((bhx * NPART) * QCNT + q) * DH + dh;
        float o = 0.f;
        #pragma unroll
        for (int n2 = 0; n2 < NPART; n2++)
            o += wv[n2] * Opart[obase + (size_t)n2 * QCNT * DH];
        As[r * CTP + c] = o;
    }
    __syncthreads();

    int rg = tid & 15, c0 = (tid >> 4) * 8;   // rows rg, rg+16; W broadcast

    // 32x128x64 GEMM step: acc[i] += Asrc[rg+16i][koff..] @ Wsm
    auto gemm64 = [&](const float* Asrc, int koff, u64 (&acc)[2][4]) {
        #pragma unroll 4
        for (int k = 0; k < 64; k++) {
            const double* Wd = (const double*)(Wsm + k * 128 + c0);
            u64 w0 = __double_as_longlong(Wd[0]);
            u64 w1 = __double_as_longlong(Wd[1]);
            u64 w2 = __double_as_longlong(Wd[2]);
            u64 w3 = __double_as_longlong(Wd[3]);
            #pragma unroll
            for (int i = 0; i < 2; i++) {
                u64 av = f2_dup(Asrc[(rg + 16 * i) * CTP + koff + k]);
                acc[i][0] = f2_fma(av, w0, acc[i][0]);
                acc[i][1] = f2_fma(av, w1, acc[i][1]);
                acc[i][2] = f2_fma(av, w2, acc[i][2]);
                acc[i][3] = f2_fma(av, w3, acc[i][3]);
            }
        }
    };

    // ---- GEMM1: z = A @ Wp (two k-halves) ----
    {
        u64 acc[2][4];
        #pragma unroll
        for (int i = 0; i < 2; i++)
            #pragma unroll
            for (int j = 0; j < 4; j++) acc[i][j] = 0ull;
        gemm64(As, 0, acc);
        __syncthreads();
        stageW(Wpm + 64 * 128, 128);
        __syncthreads();
        gemm64(As, 64, acc);
        const double* bd = (const double*)(bpv + c0);
        #pragma unroll
        for (int i = 0; i < 2; i++) {
            u64* dst = (u64*)&Bs[(rg + 16 * i) * CTP + c0];
            #pragma unroll
            for (int j = 0; j < 4; j++)
                dst[j] = f2_add(acc[i][j], __double_as_longlong(bd[j]));
        }
    }
    __syncthreads();
    // ---- + skip, stage W1[h0] k0 ----
    for (int idx = tid; idx < TROWS * 128; idx += 256) {
        int c = idx >> 5, r = idx & 31;
        Bs[r * CTP + c] += skip[((size_t)(b * DIMC + c)) * QCNT + q0 + r];
    }
    stageW(W1m, 256);
    __syncthreads();
    // ---- pre-LN: 8 threads per row ----
    {
        int r = tid >> 3, p = tid & 7;
        const float* row = &Bs[r * CTP];
        float s = 0.f, s2 = 0.f;
        #pragma unroll 4
        for (int ci = 0; ci < 16; ci++) { float x = row[p + 8 * ci]; s += x; s2 += x * x; }
        s  += __shfl_xor_sync(0xffffffffu, s, 1);
        s2 += __shfl_xor_sync(0xffffffffu, s2, 1);
        s  += __shfl_xor_sync(0xffffffffu, s, 2);
        s2 += __shfl_xor_sync(0xffffffffu, s2, 2);
        s  += __shfl_xor_sync(0xffffffffu, s, 4);
        s2 += __shfl_xor_sync(0xffffffffu, s2, 4);
        if (p == 0) {
            float mn = s * (1.f / 128.f);
            float vv = s2 * (1.f / 128.f) - mn * mn;
            sm[r] = mn; sr[r] = rsqrtf(vv + 1e-5f);
        }
    }
    __syncthreads();
    for (int idx = tid; idx < TROWS * 128; idx += 256) {
        int r = idx >> 7, c = idx & 127;
        Bs[r * CTP + c] = (Bs[r * CTP + c] - sm[r]) * sr[r] * preg[c] + preb[c];
    }
    __syncthreads();
    // ---- MLP: halves of W1/W2, each staged in two k-halves ----
    u64 acc2[2][4];
    #pragma unroll
    for (int i = 0; i < 2; i++)
        #pragma unroll
        for (int j = 0; j < 4; j++) acc2[i][j] = 0ull;
    #pragma unroll 1
    for (int half = 0; half < 2; half++) {
        // Wsm holds W1[half] k-rows [0,64) on loop entry
        u64 h[2][4];
        #pragma unroll
        for (int i = 0; i < 2; i++)
            #pragma unroll
            for (int j = 0; j < 4; j++) h[i][j] = 0ull;
        gemm64(Bs, 0, h);
        __syncthreads();
        stageW(W1m + (size_t)64 * 256 + half * 128, 256);
        __syncthreads();
        gemm64(Bs, 64, h);
        const double* b1d = (const double*)(b1v + half * 128 + c0);
        #pragma unroll
        for (int i = 0; i < 2; i++)
            #pragma unroll
            for (int j = 0; j < 4; j++) {
                float lo, hi;
                f2_unpack(lo, hi, f2_add(h[i][j], __double_as_longlong(b1d[j])));
                float g0 = 0.5f * lo * (1.f + erff(lo * 0.70710678118654752f));
                float g1 = 0.5f * hi * (1.f + erff(hi * 0.70710678118654752f));
                As[(rg + 16 * i) * CTP + c0 + 2 * j]     = g0;
                As[(rg + 16 * i) * CTP + c0 + 2 * j + 1] = g1;
            }
        __syncthreads();
        stageW(W2m + (size_t)half * 128 * 128, 128);
        __syncthreads();
        gemm64(As, 0, acc2);
        __syncthreads();
        stageW(W2m + (size_t)(half * 128 + 64) * 128, 128);
        __syncthreads();
        gemm64(As, 64, acc2);
        __syncthreads();
        if (half == 0) {
            stageW(W1m + 128, 256);    // W1[h1] k-rows [0,64)
            __syncthreads();
        }
    }
    {
        const double* b2d = (const double*)(b2v + c0);
        #pragma unroll
        for (int i = 0; i < 2; i++) {
            u64* dst = (u64*)&Bs[(rg + 16 * i) * CTP + c0];
            #pragma unroll
            for (int j = 0; j < 4; j++)
                dst[j] = f2_add(dst[j], f2_add(acc2[i][j], __double_as_longlong(b2d[j])));
        }
    }
    __syncthreads();
    // ---- post-LN: 8 threads per row ----
    {
        int r = tid >> 3, p = tid & 7;
        const float* row = &Bs[r * CTP];
        float s = 0.f, s2 = 0.f;
        #pragma unroll 4
        for (int ci = 0; ci < 16; ci++) { float x = row[p + 8 * ci]; s += x; s2 += x * x; }
        s  += __shfl_xor_sync(0xffffffffu, s, 1);
        s2 += __shfl_xor_sync(0xffffffffu, s2, 1);
        s  += __shfl_xor_sync(0xffffffffu, s, 2);
        s2 += __shfl_xor_sync(0xffffffffu, s2, 2);
        s  += __shfl_xor_sync(0xffffffffu, s, 4);
        s2 += __shfl_xor_sync(0xffffffffu, s2, 4);
        if (p == 0) {
            float mn = s * (1.f / 128.f);
            float vv = s2 * (1.f / 128.f) - mn * mn;
            sm[r] = mn; sr[r] = rsqrtf(vv + 1e-5f);
        }
    }
    __syncthreads();
    // ---- write transposed output (B, d, H, W) ----
    for (int idx = tid; idx < TROWS * 128; idx += 256) {
        int c = idx >> 5, r = idx & 31;
        float z = (Bs[r * CTP + c] - sm[r]) * sr[r] * postg[c] + postb[c];
        outp[((size_t)(b * DIMC + c)) * QCNT + q0 + r] = z;
    }
}

// ==================================================================
extern "C" void kernel_launch(void* const* d_in, const int* in_sizes, int n_in,
                              void* d_out, int out_size)
{
    const float* q     = (const float*)d_in[0];
    const float* k     = (const float*)d_in[1];
    const float* v     = (const float*)d_in[2];
    const float* skip  = (const float*)d_in[3];
    const float* lnq_g = (const float*)d_in[4];
    const float* lnq_b = (const float*)d_in[5];
    const float* Wq    = (const float*)d_in[6];
    const float* bq    = (const float*)d_in[7];
    const float* lnk_g = (const float*)d_in[8];
    const float* lnk_b = (const float*)d_in[9];
    const float* Wk    = (const float*)d_in[10];
    const float* bk    = (const float*)d_in[11];
    const float* lnv_g = (const float*)d_in[12];
    const float* lnv_b = (const float*)d_in[13];
    const float* Wv    = (const float*)d_in[14];
    const float* bv    = (const float*)d_in[15];
    const float* Wp    = (const float*)d_in[16];
    const float* bp    = (const float*)d_in[17];
    const float* pre_g = (const float*)d_in[18];
    const float* pre_b = (const float*)d_in[19];
    const float* W1    = (const float*)d_in[20];
    const float* b1    = (const float*)d_in[21];
    const float* W2    = (const float*)d_in[22];
    const float* b2    = (const float*)d_in[23];
    const float* post_g= (const float*)d_in[24];
    const float* post_b= (const float*)d_in[25];
    float* outp = (float*)d_out;

    float *qp, *kpb, *vpb, *Opart, *mlb;
    cudaGetSymbolAddress((void**)&qp,   g_qp);
    cudaGetSymbolAddress((void**)&kpb,  g_kp);
    cudaGetSymbolAddress((void**)&vpb,  g_vp);
    cudaGetSymbolAddress((void**)&Opart,g_Opart);
    cudaGetSymbolAddress((void**)&mlb,  g_ml);

    const int PROJ_SMEM = (64 * PJS + 64 * 128) * sizeof(float);                       // 65792
    const int TAIL_SMEM = (2 * TROWS * CTP + 8192 + TROWS * 4 * NPART) * sizeof(float); // 72704
    cudaFuncSetAttribute(proj_all_kernel,
                         cudaFuncAttributeMaxDynamicSharedMemorySize, PROJ_SMEM);
    cudaFuncSetAttribute(tail_kernel,
                         cudaFuncAttributeMaxDynamicSharedMemorySize, TAIL_SMEM);

    proj_all_kernel<<<648, 256, PROJ_SMEM>>>(q, k, v,
        lnq_g, lnq_b, Wq, bq, lnk_g, lnk_b, Wk, bk, lnv_g, lnv_b, Wv, bv,
        qp, kpb, vpb);

    dim3 ag(QCNT / 128, NPART, BH);
    attn_kernel<<<ag, 64>>>(qp, kpb, vpb, Opart, mlb);

    tail_kernel<<<(BB * QCNT) / TROWS, 256, TAIL_SMEM>>>(Opart, mlb, skip, Wp, bp, pre_g, pre_b,
                                           W1, b1, W2, b2, post_g, post_b, outp);
}

// round 12
// speedup vs baseline: 1.0558x; 1.0558x over previous
#include <cuda_runtime.h>
#include <math_constants.h>

// ---------------- problem constants ----------------
#define BB 2
#define NV 6
#define DIMC 128
#define QCNT 2304   // 48*48
#define KCNT 576    // 24*24
#define HEADS 4
#define DH 32
#define BH (BB*HEADS)          // 8
#define NSPLIT 2
#define KSPL (KCNT/NSPLIT)     // 288
#define NPART (NV*NSPLIT)      // 12
#define CHK 72                 // attn chunk keys (4 chunks of 72)
// q pre-scale: SCALEF * log2(e)  -> scores live in log2 domain
#define QSCALE 0.25541281188299536f

typedef unsigned long long u64;

// ---------------- f32x2 packed helpers ----------------
__device__ __forceinline__ u64 f2_fma(u64 a, u64 b, u64 c) {
    u64 d; asm("fma.rn.f32x2 %0,%1,%2,%3;" : "=l"(d) : "l"(a), "l"(b), "l"(c)); return d;
}
__device__ __forceinline__ u64 f2_mul(u64 a, u64 b) {
    u64 d; asm("mul.rn.f32x2 %0,%1,%2;" : "=l"(d) : "l"(a), "l"(b)); return d;
}
__device__ __forceinline__ u64 f2_add(u64 a, u64 b) {
    u64 d; asm("add.rn.f32x2 %0,%1,%2;" : "=l"(d) : "l"(a), "l"(b)); return d;
}
__device__ __forceinline__ u64 f2_dup(float x) {
    u64 d; asm("mov.b64 %0,{%1,%1};" : "=l"(d) : "r"(__float_as_uint(x))); return d;
}
__device__ __forceinline__ void f2_unpack(float& lo, float& hi, u64 v) {
    unsigned a, b; asm("mov.b64 {%0,%1},%2;" : "=r"(a), "=r"(b) : "l"(v));
    lo = __uint_as_float(a); hi = __uint_as_float(b);
}
__device__ __forceinline__ unsigned s2u(const void* p) {
    unsigned r;
    asm("{.reg .u64 t; cvta.to.shared.u64 t, %1; cvt.u32.u64 %0, t;}" : "=r"(r) : "l"(p));
    return r;
}
__device__ __forceinline__ void cpa16(unsigned s, const void* g) {
    asm volatile("cp.async.cg.shared.global [%0], [%1], 16;" :: "r"(s), "l"(g));
}
__device__ __forceinline__ float fexp2(float x) {
    float r; asm("ex2.approx.f32 %0, %1;" : "=f"(r) : "f"(x)); return r;
}

// ---------------- scratch (device globals; no allocation allowed) ----------------
__device__ float g_qp[BH * NV * QCNT * DH];
__device__ float g_kp[BH * NV * KCNT * DH];
__device__ float g_vp[BH * NV * KCNT * DH];
__device__ float g_Opart[BH * NPART * QCNT * DH];
__device__ float g_ml[BH * NPART * QCNT * 2];

// ==================================================================
// Kernel 1: LN + projection for q,k,v in ONE launch. 64-row tiles.
// q: blocks [0,432), k: [432,540), v: [540,648).  256 threads.
// Dynamic smem: As[64*129] + Wsm[64*128] = 65792 B -> 3 blocks/SM.
// W staged in two k-halves. Threads: rg = tid&15 owns rows rg+16i
// (conflict-free), c0 = (tid>>4)*8 (W broadcast).
// q output pre-scaled by SCALEF*log2(e) (exp2-domain softmax).
// ==================================================================
#define PJS 129
__global__ __launch_bounds__(256, 3) void proj_all_kernel(
    const float* __restrict__ qi, const float* __restrict__ ki, const float* __restrict__ vi,
    const float* __restrict__ lnqg, const float* __restrict__ lnqb,
    const float* __restrict__ Wq, const float* __restrict__ bq,
    const float* __restrict__ lnkg, const float* __restrict__ lnkb,
    const float* __restrict__ Wk, const float* __restrict__ bk,
    const float* __restrict__ lnvg, const float* __restrict__ lnvb,
    const float* __restrict__ Wv, const float* __restrict__ bv,
    float* __restrict__ qo, float* __restrict__ ko, float* __restrict__ vo)
{
    extern __shared__ float dynP[];
    float* As  = dynP;                  // 64*129
    float* Wsm = dynP + 64 * PJS;       // 64*128
    __shared__ float s_mean[64], s_rstd[64];
    int blk = blockIdx.x;
    int tid = threadIdx.x;

    const float* X; const float* lng; const float* lnb;
    const float* Wt; const float* biasv; float* outp; int S, local; float oscale;
    if (blk < 432)      { X = qi; lng = lnqg; lnb = lnqb; Wt = Wq; biasv = bq; outp = qo; S = QCNT; local = blk;       oscale = QSCALE; }
    else if (blk < 540) { X = ki; lng = lnkg; lnb = lnkb; Wt = Wk; biasv = bk; outp = ko; S = KCNT; local = blk - 432; oscale = 1.f; }
    else                { X = vi; lng = lnvg; lnb = lnvb; Wt = Wv; biasv = bv; outp = vo; S = KCNT; local = blk - 540; oscale = 1.f; }

    int tiles = S >> 6;
    int t = local % tiles;
    int bn = local / tiles;            // b*6+n
    int b = bn / NV, n = bn % NV;
    int s0 = t * 64;
    const float* Xb = X + (size_t)bn * DIMC * S;

    // load A tile (coalesced) + stage W k-half0
    for (int idx = tid; idx < 64 * 128; idx += 256) {
        int c = idx >> 6, r = idx & 63;
        As[r * PJS + c] = Xb[(size_t)c * S + s0 + r];
    }
    {
        const float4* Wg = (const float4*)Wt;
        float4* Ws4 = (float4*)Wsm;
        for (int i = tid; i < 2048; i += 256) Ws4[i] = Wg[i];
    }
    __syncthreads();
    // ---- LN stats: 4 threads per row, shfl butterfly ----
    {
        int r = tid >> 2, p = tid & 3;
        const float* row = &As[r * PJS];
        float s = 0.f, s2 = 0.f;
        #pragma unroll 8
        for (int ci = 0; ci < 32; ci++) { float x = row[p + 4 * ci]; s += x; s2 += x * x; }
        s  += __shfl_xor_sync(0xffffffffu, s, 1);
        s2 += __shfl_xor_sync(0xffffffffu, s2, 1);
        s  += __shfl_xor_sync(0xffffffffu, s, 2);
        s2 += __shfl_xor_sync(0xffffffffu, s2, 2);
        if (p == 0) {
            float mn = s * (1.f / 128.f);
            float vv = s2 * (1.f / 128.f) - mn * mn;
            s_mean[r] = mn; s_rstd[r] = rsqrtf(vv + 1e-5f);
        }
    }
    __syncthreads();
    for (int idx = tid; idx < 64 * 128; idx += 256) {
        int r = idx >> 7, c = idx & 127;
        As[r * PJS + c] = (As[r * PJS + c] - s_mean[r]) * s_rstd[r] * lng[c] + lnb[c];
    }
    __syncthreads();

    // GEMM 64x128 * 128x128 over two k-halves
    int rg = tid & 15;
    int c0 = (tid >> 4) * 8;
    u64 acc[4][4];
    #pragma unroll
    for (int i = 0; i < 4; i++)
        #pragma unroll
        for (int j = 0; j < 4; j++) acc[i][j] = 0ull;

    #pragma unroll 1
    for (int kk = 0; kk < 2; kk++) {
        #pragma unroll 4
        for (int k = 0; k < 64; k++) {
            const double* Wd = (const double*)(Wsm + k * 128 + c0);
            u64 w0 = __double_as_longlong(Wd[0]);
            u64 w1 = __double_as_longlong(Wd[1]);
            u64 w2 = __double_as_longlong(Wd[2]);
            u64 w3 = __double_as_longlong(Wd[3]);
            #pragma unroll
            for (int i = 0; i < 4; i++) {
                u64 av = f2_dup(As[(rg + 16 * i) * PJS + kk * 64 + k]);
                acc[i][0] = f2_fma(av, w0, acc[i][0]);
                acc[i][1] = f2_fma(av, w1, acc[i][1]);
                acc[i][2] = f2_fma(av, w2, acc[i][2]);
                acc[i][3] = f2_fma(av, w3, acc[i][3]);
            }
        }
        if (kk == 0) {
            __syncthreads();
            const float4* Wg = (const float4*)(Wt + 64 * 128);
            float4* Ws4 = (float4*)Wsm;
            for (int i = tid; i < 2048; i += 256) Ws4[i] = Wg[i];
            __syncthreads();
        }
    }
    const double* Bd = (const double*)(biasv + c0);
    u64 bb0 = __double_as_longlong(Bd[0]);
    u64 bb1 = __double_as_longlong(Bd[1]);
    u64 bb2 = __double_as_longlong(Bd[2]);
    u64 bb3 = __double_as_longlong(Bd[3]);
    u64 sc = f2_dup(oscale);
    int head = c0 >> 5, dh0 = c0 & 31;
    #pragma unroll
    for (int i = 0; i < 4; i++) {
        int qrow = s0 + rg + 16 * i;
        u64* dst = (u64*)(outp + ((((size_t)(b * HEADS + head) * NV + n) * S + qrow) * DH + dh0));
        dst[0] = f2_mul(f2_add(acc[i][0], bb0), sc);
        dst[1] = f2_mul(f2_add(acc[i][1], bb1), sc);
        dst[2] = f2_mul(f2_add(acc[i][2], bb2), sc);
        dst[3] = f2_mul(f2_add(acc[i][3], bb3), sc);
    }
}

// ==================================================================
// Kernel 2: per-(view,split) flash attention partials. 2 queries/thread.
// grid (18, 12, 8), 64 threads. 288 keys in 4x72 chunks, cp.async
// double-buffered. smem 36KB -> 5 blocks/SM.  exp2-domain softmax.
// ==================================================================
__device__ __forceinline__ void attn_chunk(
    const float4* Ks, const float4* Vs,
    const u64 qu[2][16], u64 Ov[2][16],
    float& m0, float& m1, float& l0, float& l1)
{
    #pragma unroll 1
    for (int g = 0; g < CHK / 8; g++) {
        float sc0[8], sc1[8];
        #pragma unroll
        for (int j = 0; j < 8; j++) {
            const double2* Kr = (const double2*)&Ks[(g * 8 + j) * 8];
            u64 a00 = 0, a01 = 0, a10 = 0, a11 = 0;
            #pragma unroll
            for (int i = 0; i < 4; i++) {
                double2 d0 = Kr[2 * i];
                double2 d1 = Kr[2 * i + 1];
                u64 k0 = __double_as_longlong(d0.x), k1 = __double_as_longlong(d0.y);
                u64 k2 = __double_as_longlong(d1.x), k3 = __double_as_longlong(d1.y);
                a00 = f2_fma(qu[0][4 * i + 0], k0, a00);
                a01 = f2_fma(qu[0][4 * i + 1], k1, a01);
                a00 = f2_fma(qu[0][4 * i + 2], k2, a00);
                a01 = f2_fma(qu[0][4 * i + 3], k3, a01);
                a10 = f2_fma(qu[1][4 * i + 0], k0, a10);
                a11 = f2_fma(qu[1][4 * i + 1], k1, a11);
                a10 = f2_fma(qu[1][4 * i + 2], k2, a10);
                a11 = f2_fma(qu[1][4 * i + 3], k3, a11);
            }
            float lo, hi;
            f2_unpack(lo, hi, f2_add(a00, a01)); sc0[j] = lo + hi;
            f2_unpack(lo, hi, f2_add(a10, a11)); sc1[j] = lo + hi;
        }
        float gm0 = sc0[0], gm1 = sc1[0];
        #pragma unroll
        for (int j = 1; j < 8; j++) { gm0 = fmaxf(gm0, sc0[j]); gm1 = fmaxf(gm1, sc1[j]); }
        if (gm0 > m0) {
            float sf = fexp2(m0 - gm0);   // m=-inf -> 0
            l0 *= sf;
            u64 s2 = f2_dup(sf);
            #pragma unroll
            for (int e = 0; e < 16; e++) Ov[0][e] = f2_mul(Ov[0][e], s2);
            m0 = gm0;
        }
        if (gm1 > m1) {
            float sf = fexp2(m1 - gm1);
            l1 *= sf;
            u64 s2 = f2_dup(sf);
            #pragma unroll
            for (int e = 0; e < 16; e++) Ov[1][e] = f2_mul(Ov[1][e], s2);
            m1 = gm1;
        }
        #pragma unroll
        for (int j = 0; j < 8; j++) {
            float p0 = fexp2(sc0[j] - m0); l0 += p0;
            float p1 = fexp2(sc1[j] - m1); l1 += p1;
            u64 pp0 = f2_dup(p0);
            u64 pp1 = f2_dup(p1);
            const double2* Vr = (const double2*)&Vs[(g * 8 + j) * 8];
            #pragma unroll
            for (int i = 0; i < 4; i++) {
                double2 v0 = Vr[2 * i];
                double2 v1 = Vr[2 * i + 1];
                u64 x0 = __double_as_longlong(v0.x), x1 = __double_as_longlong(v0.y);
                u64 x2 = __double_as_longlong(v1.x), x3 = __double_as_longlong(v1.y);
                Ov[0][4 * i + 0] = f2_fma(pp0, x0, Ov[0][4 * i + 0]);
                Ov[0][4 * i + 1] = f2_fma(pp0, x1, Ov[0][4 * i + 1]);
                Ov[0][4 * i + 2] = f2_fma(pp0, x2, Ov[0][4 * i + 2]);
                Ov[0][4 * i + 3] = f2_fma(pp0, x3, Ov[0][4 * i + 3]);
                Ov[1][4 * i + 0] = f2_fma(pp1, x0, Ov[1][4 * i + 0]);
                Ov[1][4 * i + 1] = f2_fma(pp1, x1, Ov[1][4 * i + 1]);
                Ov[1][4 * i + 2] = f2_fma(pp1, x2, Ov[1][4 * i + 2]);
                Ov[1][4 * i + 3] = f2_fma(pp1, x3, Ov[1][4 * i + 3]);
            }
        }
    }
}

__global__ __launch_bounds__(64, 5) void attn_kernel(
    const float* __restrict__ qp, const float* __restrict__ kp,
    const float* __restrict__ vp, float* __restrict__ Opart,
    float* __restrict__ ml)
{
    __shared__ float4 Ksm[2][CHK * 8];
    __shared__ float4 Vsm[2][CHK * 8];
    int qt = blockIdx.x;
    int ns = blockIdx.y;                 // n*2 + split
    int bh = blockIdx.z;
    int n = ns >> 1, split = ns & 1;
    int tid = threadIdx.x;
    size_t view = (size_t)bh * NV + n;
    size_t view2 = view * NSPLIT + split;
    int base = split * KSPL;

    const float4* Kb = (const float4*)(kp + view * KCNT * DH);
    const float4* Vb = (const float4*)(vp + view * KCNT * DH);

    // issue a CHK-key (K,V) stage into buffer buf
    auto issue = [&](int st, int buf) {
        const float4* Kg = Kb + (size_t)(base + st * CHK) * 8;
        const float4* Vg = Vb + (size_t)(base + st * CHK) * 8;
        #pragma unroll
        for (int i = 0; i < CHK * 8 / 64; i++) {
            int f = i * 64 + tid;
            cpa16(s2u(&Ksm[buf][f]), Kg + f);
            cpa16(s2u(&Vsm[buf][f]), Vg + f);
        }
        asm volatile("cp.async.commit_group;");
    };

    issue(0, 0);
    issue(1, 1);

    u64 qu[2][16];
    #pragma unroll
    for (int s = 0; s < 2; s++) {
        const u64* qrow = (const u64*)(qp + (view * QCNT + qt * 128 + s * 64 + tid) * DH);
        #pragma unroll
        for (int e = 0; e < 16; e++) qu[s][e] = qrow[e];   // pre-scaled by QSCALE
    }
    u64 Ov[2][16];
    #pragma unroll
    for (int s = 0; s < 2; s++)
        #pragma unroll
        for (int e = 0; e < 16; e++) Ov[s][e] = 0ull;
    float m0 = -CUDART_INF_F, m1 = -CUDART_INF_F, l0 = 0.f, l1 = 0.f;

    asm volatile("cp.async.wait_group 1;");
    __syncthreads();
    attn_chunk(Ksm[0], Vsm[0], qu, Ov, m0, m1, l0, l1);
    __syncthreads();
    issue(2, 0);
    asm volatile("cp.async.wait_group 1;");
    __syncthreads();
    attn_chunk(Ksm[1], Vsm[1], qu, Ov, m0, m1, l0, l1);
    __syncthreads();
    issue(3, 1);
    asm volatile("cp.async.wait_group 1;");
    __syncthreads();
    attn_chunk(Ksm[0], Vsm[0], qu, Ov, m0, m1, l0, l1);
    __syncthreads();
    asm volatile("cp.async.wait_group 0;");
    __syncthreads();
    attn_chunk(Ksm[1], Vsm[1], qu, Ov, m0, m1, l0, l1);

    #pragma unroll
    for (int s = 0; s < 2; s++) {
        size_t orow = view2 * QCNT + qt * 128 + s * 64 + tid;
        u64* dst = (u64*)(Opart + orow * DH);
        #pragma unroll
        for (int e = 0; e < 16; e++) dst[e] = Ov[s][e];
        ml[orow * 2]     = s ? m1 : m0;
        ml[orow * 2 + 1] = s ? l1 : l0;
    }
}

// ==================================================================
// Kernel 3: fused combine(12) + out-proj + skip + preLN + MLP + postLN
//           + transposed store. 256 threads, 16-row tiles (288 blocks).
// Weights staged in 64-k-row halves (Wsm 32KB). smem 52.5KB.
// Threads: rg = tid&15 owns row rg; c0 = (tid>>4)*8 (W broadcast).
// Combine uses exp2 (ml values are log2-domain).
// ==================================================================
#define CTP 130
#define TROWS 16
__global__ __launch_bounds__(256, 3) void tail_kernel(
    const float* __restrict__ Opart, const float* __restrict__ ml,
    const float* __restrict__ skip,
    const float* __restrict__ Wpm, const float* __restrict__ bpv,
    const float* __restrict__ preg, const float* __restrict__ preb,
    const float* __restrict__ W1m, const float* __restrict__ b1v,
    const float* __restrict__ W2m, const float* __restrict__ b2v,
    const float* __restrict__ postg, const float* __restrict__ postb,
    float* __restrict__ outp)
{
    extern __shared__ float dynT[];
    float* As  = dynT;                       // TROWS*CTP
    float* Bs  = As + TROWS * CTP;           // TROWS*CTP
    float* Wsm = Bs + TROWS * CTP;           // 64*128 = 8192
    float* sW  = Wsm + 8192;                 // TROWS*4*NPART = 768
    __shared__ float sm[TROWS], sr[TROWS];
    int tid = threadIdx.x;
    int gr0 = blockIdx.x * TROWS;       // rows are b*2304+q
    int b = gr0 / QCNT, q0 = gr0 - b * QCNT;

    // stage-weight helper: 64 k-rows x 128 cols from row-major [.,ld]
    auto stageW = [&](const float* Wg0, int ld) {
        #pragma unroll 2
        for (int i = tid; i < 2048; i += 256) {
            int k = i >> 5, c4 = i & 31;
            ((float4*)Wsm)[k * 32 + c4] = ((const float4*)(Wg0 + (size_t)k * ld))[c4];
        }
    };

    // ---- combine weights (tid<64: one per (row, head)) + stage Wp k0 ----
    if (tid < 64) {
        int r = tid >> 2, head = tid & 3;
        int q = q0 + r;
        size_t bhx = (size_t)b * HEADS + head;
        size_t rowbase = (bhx * NPART) * QCNT + q;
        float mv[NPART], lv[NPART], M = -CUDART_INF_F;
        #pragma unroll
        for (int n2 = 0; n2 < NPART; n2++) {
            size_t row = rowbase + (size_t)n2 * QCNT;
            mv[n2] = ml[row * 2];
            lv[n2] = ml[row * 2 + 1];
            M = fmaxf(M, mv[n2]);
        }
        float L = 0.f;
        float w[NPART];
        #pragma unroll
        for (int n2 = 0; n2 < NPART; n2++) {
            w[n2] = exp2f(mv[n2] - M);     // log2-domain partial maxima
            L += w[n2] * lv[n2];
        }
        float Linv = __fdividef(1.f, L);
        #pragma unroll
        for (int n2 = 0; n2 < NPART; n2++)
            sW[tid * NPART + n2] = w[n2] * Linv;
    }
    stageW(Wpm, 128);
    __syncthreads();

    // ---- combine 12 partials into As ----
    for (int idx = tid; idx < TROWS * 128; idx += 256) {
        int r = idx >> 7, c = idx & 127;
        int q = q0 + r;
        int head = c >> 5, dh = c & 31;
        size_t bhx = (size_t)b * HEADS + head;
        const float* wv = &sW[(r * 4 + head) * NPART];
        size_t obase = ((bhx * NPART) * QCNT + q) * DH + dh;
        float o = 0.f;
        #pragma unroll
        for (int n2 = 0; n2 < NPART; n2++)
            o += wv[n2] * Opart[obase + (size_t)n2 * QCNT * DH];
        As[r * CTP + c] = o;
    }
    __syncthreads();

    int rg = tid & 15, c0 = (tid >> 4) * 8;   // row rg; W broadcast

    // generic 16x128x64 GEMM step: acc += Asrc[rg][koff..] @ Wsm
    auto gemm64 = [&](const float* Asrc, int koff, u64 acc[4]) {
        #pragma unroll 4
        for (int k = 0; k < 64; k++) {
            const double* Wd = (const double*)(Wsm + k * 128 + c0);
            u64 w0 = __double_as_longlong(Wd[0]);
            u64 w1 = __double_as_longlong(Wd[1]);
            u64 w2 = __double_as_longlong(Wd[2]);
            u64 w3 = __double_as_longlong(Wd[3]);
            u64 av = f2_dup(Asrc[rg * CTP + koff + k]);
            acc[0] = f2_fma(av, w0, acc[0]);
            acc[1] = f2_fma(av, w1, acc[1]);
            acc[2] = f2_fma(av, w2, acc[2]);
            acc[3] = f2_fma(av, w3, acc[3]);
        }
    };

    // ---- GEMM1: z = A @ Wp (two k-halves) ----
    {
        u64 acc[4] = {0ull, 0ull, 0ull, 0ull};
        gemm64(As, 0, acc);
        __syncthreads();
        stageW(Wpm + 64 * 128, 128);
        __syncthreads();
        gemm64(As, 64, acc);
        const double* bd = (const double*)(bpv + c0);
        u64* dst = (u64*)&Bs[rg * CTP + c0];
        #pragma unroll
        for (int j = 0; j < 4; j++)
            dst[j] = f2_add(acc[j], __double_as_longlong(bd[j]));
    }
    __syncthreads();
    // ---- + skip, stage W1[h0] k0 ----
    for (int idx = tid; idx < TROWS * 128; idx += 256) {
        int c = idx >> 4, r = idx & (TROWS - 1);
        Bs[r * CTP + c] += skip[((size_t)(b * DIMC + c)) * QCNT + q0 + r];
    }
    stageW(W1m, 256);
    __syncthreads();
    // ---- pre-LN: 16 threads per row ----
    {
        int r = tid >> 4, p = tid & 15;
        const float* row = &Bs[r * CTP];
        float s = 0.f, s2 = 0.f;
        #pragma unroll
        for (int ci = 0; ci < 8; ci++) { float x = row[p + 16 * ci]; s += x; s2 += x * x; }
        s  += __shfl_xor_sync(0xffffffffu, s, 1);
        s2 += __shfl_xor_sync(0xffffffffu, s2, 1);
        s  += __shfl_xor_sync(0xffffffffu, s, 2);
        s2 += __shfl_xor_sync(0xffffffffu, s2, 2);
        s  += __shfl_xor_sync(0xffffffffu, s, 4);
        s2 += __shfl_xor_sync(0xffffffffu, s2, 4);
        s  += __shfl_xor_sync(0xffffffffu, s, 8);
        s2 += __shfl_xor_sync(0xffffffffu, s2, 8);
        if (p == 0) {
            float mn = s * (1.f / 128.f);
            float vv = s2 * (1.f / 128.f) - mn * mn;
            sm[r] = mn; sr[r] = rsqrtf(vv + 1e-5f);
        }
    }
    __syncthreads();
    for (int idx = tid; idx < TROWS * 128; idx += 256) {
        int r = idx >> 7, c = idx & 127;
        Bs[r * CTP + c] = (Bs[r * CTP + c] - sm[r]) * sr[r] * preg[c] + preb[c];
    }
    __syncthreads();
    // ---- MLP: halves h of W1/W2, each staged in two k-halves ----
    u64 acc2[4] = {0ull, 0ull, 0ull, 0ull};
    #pragma unroll 1
    for (int half = 0; half < 2; half++) {
        // Wsm holds W1[half] k-rows [0,64) on loop entry
        u64 h[4] = {0ull, 0ull, 0ull, 0ull};
        gemm64(Bs, 0, h);
        __syncthreads();
        stageW(W1m + (size_t)64 * 256 + half * 128, 256);
        __syncthreads();
        gemm64(Bs, 64, h);
        const double* b1d = (const double*)(b1v + half * 128 + c0);
        #pragma unroll
        for (int j = 0; j < 4; j++) {
            float lo, hi;
            f2_unpack(lo, hi, f2_add(h[j], __double_as_longlong(b1d[j])));
            float g0 = 0.5f * lo * (1.f + erff(lo * 0.70710678118654752f));
            float g1 = 0.5f * hi * (1.f + erff(hi * 0.70710678118654752f));
            As[rg * CTP + c0 + 2 * j]     = g0;
            As[rg * CTP + c0 + 2 * j + 1] = g1;
        }
        __syncthreads();
        stageW(W2m + (size_t)half * 128 * 128, 128);
        __syncthreads();
        gemm64(As, 0, acc2);
        __syncthreads();
        stageW(W2m + (size_t)(half * 128 + 64) * 128, 128);
        __syncthreads();
        gemm64(As, 64, acc2);
        __syncthreads();
        if (half == 0) {
            stageW(W1m + 128, 256);    // W1[h1] k-rows [0,64)
            __syncthreads();
        }
    }
    {
        const double* b2d = (const double*)(b2v + c0);
        u64* dst = (u64*)&Bs[rg * CTP + c0];
        #pragma unroll
        for (int j = 0; j < 4; j++)
            dst[j] = f2_add(dst[j], f2_add(acc2[j], __double_as_longlong(b2d[j])));
    }
    __syncthreads();
    // ---- post-LN: 16 threads per row ----
    {
        int r = tid >> 4, p = tid & 15;
        const float* row = &Bs[r * CTP];
        float s = 0.f, s2 = 0.f;
        #pragma unroll
        for (int ci = 0; ci < 8; ci++) { float x = row[p + 16 * ci]; s += x; s2 += x * x; }
        s  += __shfl_xor_sync(0xffffffffu, s, 1);
        s2 += __shfl_xor_sync(0xffffffffu, s2, 1);
        s  += __shfl_xor_sync(0xffffffffu, s, 2);
        s2 += __shfl_xor_sync(0xffffffffu, s2, 2);
        s  += __shfl_xor_sync(0xffffffffu, s, 4);
        s2 += __shfl_xor_sync(0xffffffffu, s2, 4);
        s  += __shfl_xor_sync(0xffffffffu, s, 8);
        s2 += __shfl_xor_sync(0xffffffffu, s2, 8);
        if (p == 0) {
            float mn = s * (1.f / 128.f);
            float vv = s2 * (1.f / 128.f) - mn * mn;
            sm[r] = mn; sr[r] = rsqrtf(vv + 1e-5f);
        }
    }
    __syncthreads();
    // ---- write transposed output (B, d, H, W) ----
    for (int idx = tid; idx < TROWS * 128; idx += 256) {
        int c = idx >> 4, r = idx & (TROWS - 1);
        float z = (Bs[r * CTP + c] - sm[r]) * sr[r] * postg[c] + postb[c];
        outp[((size_t)(b * DIMC + c)) * QCNT + q0 + r] = z;
    }
}

// ==================================================================
extern "C" void kernel_launch(void* const* d_in, const int* in_sizes, int n_in,
                              void* d_out, int out_size)
{
    const float* q     = (const float*)d_in[0];
    const float* k     = (const float*)d_in[1];
    const float* v     = (const float*)d_in[2];
    const float* skip  = (const float*)d_in[3];
    const float* lnq_g = (const float*)d_in[4];
    const float* lnq_b = (const float*)d_in[5];
    const float* Wq    = (const float*)d_in[6];
    const float* bq    = (const float*)d_in[7];
    const float* lnk_g = (const float*)d_in[8];
    const float* lnk_b = (const float*)d_in[9];
    const float* Wk    = (const float*)d_in[10];
    const float* bk    = (const float*)d_in[11];
    const float* lnv_g = (const float*)d_in[12];
    const float* lnv_b = (const float*)d_in[13];
    const float* Wv    = (const float*)d_in[14];
    const float* bv    = (const float*)d_in[15];
    const float* Wp    = (const float*)d_in[16];
    const float* bp    = (const float*)d_in[17];
    const float* pre_g = (const float*)d_in[18];
    const float* pre_b = (const float*)d_in[19];
    const float* W1    = (const float*)d_in[20];
    const float* b1    = (const float*)d_in[21];
    const float* W2    = (const float*)d_in[22];
    const float* b2    = (const float*)d_in[23];
    const float* post_g= (const float*)d_in[24];
    const float* post_b= (const float*)d_in[25];
    float* outp = (float*)d_out;

    float *qp, *kpb, *vpb, *Opart, *mlb;
    cudaGetSymbolAddress((void**)&qp,   g_qp);
    cudaGetSymbolAddress((void**)&kpb,  g_kp);
    cudaGetSymbolAddress((void**)&vpb,  g_vp);
    cudaGetSymbolAddress((void**)&Opart,g_Opart);
    cudaGetSymbolAddress((void**)&mlb,  g_ml);

    const int PROJ_SMEM = (64 * PJS + 64 * 128) * sizeof(float);                        // 65792
    const int TAIL_SMEM = (2 * TROWS * CTP + 8192 + TROWS * 4 * NPART) * sizeof(float); // 52480
    cudaFuncSetAttribute(proj_all_kernel,
                         cudaFuncAttributeMaxDynamicSharedMemorySize, PROJ_SMEM);
    cudaFuncSetAttribute(tail_kernel,
                         cudaFuncAttributeMaxDynamicSharedMemorySize, TAIL_SMEM);

    proj_all_kernel<<<648, 256, PROJ_SMEM>>>(q, k, v,
        lnq_g, lnq_b, Wq, bq, lnk_g, lnk_b, Wk, bk, lnv_g, lnv_b, Wv, bv,
        qp, kpb, vpb);

    dim3 ag(QCNT / 128, NPART, BH);
    attn_kernel<<<ag, 64>>>(qp, kpb, vpb, Opart, mlb);

    tail_kernel<<<(BB * QCNT) / TROWS, 256, TAIL_SMEM>>>(Opart, mlb, skip, Wp, bp, pre_g, pre_b,
                                           W1, b1, W2, b2, post_g, post_b, outp);
}